// round 1
// baseline (speedup 1.0000x reference)
#include <cuda_runtime.h>
#include <math.h>

// Problem constants
#define BB      16
#define NNODE   64
#define FIN     128
#define FHID    256
#define ODIM    768
#define HT      1536   // translate hidden
#define DR      770
#define HR      1540
#define NEDGE   65536  // B*N*N
#define NROW    1024   // B*N

// ---------------- scratch (device globals; no runtime allocation) ----------
__device__ float g_agg[NROW * 256];          // GIN aggregated features [B*N, 2*FIN]
__device__ float g_U[NROW * HT];             // xo @ W1t[2:770]
__device__ float g_V[NROW * HT];             // xo @ W1t[770:1538]
__device__ float g_na[(size_t)NEDGE * ODIM]; // new_adjs pre-symmetrize [e, f]  (201 MB)
__device__ float g_part[NROW * 2 * HT];      // per-(b,i) BN partial sums [bi][sum(1536)|sq(1536)]
__device__ float g_c1[HT], g_c2[HT];         // folded BN scale/shift

__device__ __forceinline__ float elu_f(float x) {
    return x > 0.f ? x : (__expf(x) - 1.f);
}

// ---------------- kernel 1: agg[b,i,c,f] = sum_j A_c[b,i,j] * x[b,j,f] ------
__global__ void k_agg(const float* __restrict__ x, const float* __restrict__ adjs,
                      const float* __restrict__ flags) {
    int bi = blockIdx.x;            // b*64 + i
    int b = bi >> 6, i = bi & 63;
    int f = threadIdx.x;            // 0..127
    __shared__ float a0s[64], a1s[64];
    float fi = flags[b * 64 + i];
    if (threadIdx.x < 64) {
        int j = threadIdx.x;
        float fj = flags[b * 64 + j];
        float a = adjs[(size_t)bi * 64 + j];
        float m = fi * fj;
        a0s[j] = a * m;
        a1s[j] = (1.f - a) * m;
    }
    __syncthreads();
    float s0 = 0.f, s1 = 0.f;
    const float* xb = x + (size_t)b * NNODE * FIN;
    #pragma unroll 4
    for (int j = 0; j < 64; j++) {
        float xv = xb[j * FIN + f];
        s0 += a0s[j] * xv;
        s1 += a1s[j] * xv;
    }
    g_agg[bi * 256 + f] = s0;
    g_agg[bi * 256 + 128 + f] = s1;
}

// ---------------- kernel 2: GIN MLPs -> x_o (written directly to output) ---
__global__ void k_gin(const float* __restrict__ x, const float* __restrict__ flags,
                      const float* __restrict__ Wg, const float* __restrict__ bg,
                      const float* __restrict__ Wout, const float* __restrict__ bout,
                      float* __restrict__ out_xo) {
    __shared__ float aggs[8][256];
    __shared__ float xs[8][128];
    __shared__ float hs[8][256];
    __shared__ float fl[8];
    int r0 = blockIdx.x * 8;        // 128 blocks, 8 rows each
    int t = threadIdx.x;            // 256 threads
    for (int idx = t; idx < 8 * 256; idx += 256)
        aggs[idx >> 8][idx & 255] = g_agg[r0 * 256 + idx];
    for (int idx = t; idx < 8 * 128; idx += 256)
        xs[idx >> 7][idx & 127] = x[(size_t)r0 * 128 + idx];
    if (t < 8) fl[t] = flags[r0 + t];
    __syncthreads();

    // h = elu(agg @ Wg + bg) * flag   (Wg: [256,256])
    {
        float acc[8];
        float bgv = bg[t];
        #pragma unroll
        for (int r = 0; r < 8; r++) acc[r] = bgv;
        for (int k = 0; k < 256; k++) {
            float w = Wg[k * 256 + t];
            #pragma unroll
            for (int r = 0; r < 8; r++) acc[r] += aggs[r][k] * w;
        }
        #pragma unroll
        for (int r = 0; r < 8; r++) hs[r][t] = elu_f(acc[r]) * fl[r];
    }
    __syncthreads();

    // xo = tanh([x,h] @ Wout + bout) * flag   (Wout: [384,768])
    float acc[3][8];
    #pragma unroll
    for (int c = 0; c < 3; c++) {
        float bo = bout[t + c * 256];
        #pragma unroll
        for (int r = 0; r < 8; r++) acc[c][r] = bo;
    }
    for (int k = 0; k < 128; k++) {
        float o[8];
        #pragma unroll
        for (int r = 0; r < 8; r++) o[r] = xs[r][k];
        #pragma unroll
        for (int c = 0; c < 3; c++) {
            float w = Wout[k * 768 + t + c * 256];
            #pragma unroll
            for (int r = 0; r < 8; r++) acc[c][r] += o[r] * w;
        }
    }
    for (int k = 0; k < 256; k++) {
        float o[8];
        #pragma unroll
        for (int r = 0; r < 8; r++) o[r] = hs[r][k];
        #pragma unroll
        for (int c = 0; c < 3; c++) {
            float w = Wout[(128 + k) * 768 + t + c * 256];
            #pragma unroll
            for (int r = 0; r < 8; r++) acc[c][r] += o[r] * w;
        }
    }
    #pragma unroll
    for (int c = 0; c < 3; c++)
        #pragma unroll
        for (int r = 0; r < 8; r++)
            out_xo[(size_t)(r0 + r) * 768 + t + c * 256] = tanhf(acc[c][r]) * fl[r];
}

// ---------------- kernel 3: U,V = xo @ W1t[2:770], xo @ W1t[770:1538] -------
__global__ void k_uv(const float* __restrict__ xo, const float* __restrict__ W1t) {
    __shared__ float As[8][128];
    __shared__ float Bs[8][128];
    int t = threadIdx.x;
    int m0 = blockIdx.y * 128;                // rows of xo
    int ng0 = blockIdx.x * 128;               // 0..3071 combined U|V column
    const int isU = (ng0 < HT);
    const float* Bbase = W1t + (size_t)(isU ? 2 : 770) * HT + (isU ? ng0 : ng0 - HT);
    int m = t >> 1, h4 = (t & 1) * 4;
    const float* pA = xo + (size_t)(m0 + m) * 768 + h4;
    int kkB = t >> 5, c4 = (t & 31) * 4;
    int m_base = (t >> 4) * 8, n_base = (t & 15) * 8;

    float acc[8][8];
    #pragma unroll
    for (int a = 0; a < 8; a++)
        #pragma unroll
        for (int bq = 0; bq < 8; bq++) acc[a][bq] = 0.f;

    for (int k0 = 0; k0 < 768; k0 += 8) {
        float4 av = *(const float4*)(pA + k0);
        float4 bv = *(const float4*)(Bbase + (size_t)(k0 + kkB) * HT + c4);
        __syncthreads();
        As[h4 + 0][m] = av.x; As[h4 + 1][m] = av.y;
        As[h4 + 2][m] = av.z; As[h4 + 3][m] = av.w;
        *(float4*)&Bs[kkB][c4] = bv;
        __syncthreads();
        #pragma unroll
        for (int kk = 0; kk < 8; kk++) {
            float a[8], bb[8];
            *(float4*)(a)     = *(const float4*)&As[kk][m_base];
            *(float4*)(a + 4) = *(const float4*)&As[kk][m_base + 4];
            *(float4*)(bb)     = *(const float4*)&Bs[kk][n_base];
            *(float4*)(bb + 4) = *(const float4*)&Bs[kk][n_base + 4];
            #pragma unroll
            for (int mi = 0; mi < 8; mi++)
                #pragma unroll
                for (int ni = 0; ni < 8; ni++)
                    acc[mi][ni] += a[mi] * bb[ni];
        }
    }
    float* Obase = isU ? g_U : g_V;
    int c0 = isU ? ng0 : ng0 - HT;
    #pragma unroll
    for (int mi = 0; mi < 8; mi++) {
        float* prow = Obase + (size_t)(m0 + m_base + mi) * HT + c0 + n_base;
        *(float4*)(prow)     = make_float4(acc[mi][0], acc[mi][1], acc[mi][2], acc[mi][3]);
        *(float4*)(prow + 4) = make_float4(acc[mi][4], acc[mi][5], acc[mi][6], acc[mi][7]);
    }
}

// ---------------- kernel 4: BN stats partials over edges (per (b,i)) -------
__global__ void k_stats(const float* __restrict__ adjs, const float* __restrict__ flags,
                        const float* __restrict__ W1t) {
    int bi = blockIdx.x;
    int b = bi >> 6, i = bi & 63;
    int t = threadIdx.x;  // 256
    __shared__ float Ur[HT];
    __shared__ float a0s[64], a1s[64];
    for (int k = t; k < HT; k += 256) Ur[k] = g_U[(size_t)bi * HT + k];
    if (t < 64) {
        int j = t;
        float m = flags[b * 64 + i] * flags[b * 64 + j];
        float a = adjs[(size_t)bi * 64 + j];
        a0s[j] = a * m;
        a1s[j] = (1.f - a) * m;
    }
    __syncthreads();
    float w0[6], w1[6], u[6], sum[6], sq[6];
    #pragma unroll
    for (int s = 0; s < 6; s++) {
        int k = t + s * 256;
        w0[s] = W1t[k];           // row 0 (a0 channel)
        w1[s] = W1t[HT + k];      // row 1 (a1 channel)
        u[s] = Ur[k];
        sum[s] = 0.f; sq[s] = 0.f;
    }
    const float* Vb = g_V + (size_t)(b * 64) * HT;
    for (int j = 0; j < 64; j++) {
        float a0 = a0s[j], a1 = a1s[j];
        const float* Vr = Vb + (size_t)j * HT;
        #pragma unroll
        for (int s = 0; s < 6; s++) {
            float z = u[s] + Vr[t + s * 256] + a0 * w0[s] + a1 * w1[s];
            sum[s] += z;
            sq[s] += z * z;
        }
    }
    #pragma unroll
    for (int s = 0; s < 6; s++) {
        g_part[(size_t)bi * 3072 + t + s * 256] = sum[s];
        g_part[(size_t)bi * 3072 + HT + t + s * 256] = sq[s];
    }
}

// ---------------- kernel 5: finalize BN constants ---------------------------
__global__ void k_stats2(const float* __restrict__ b1t, const float* __restrict__ gamma,
                         const float* __restrict__ beta) {
    int k = blockIdx.x * 256 + threadIdx.x;  // 6 blocks -> 1536
    float s = 0.f, q = 0.f;
    for (int bi = 0; bi < NROW; bi++) {
        s += g_part[(size_t)bi * 3072 + k];
        q += g_part[(size_t)bi * 3072 + HT + k];
    }
    const float inv = 1.f / 65536.f;
    float mu_z = s * inv;
    float var = fmaxf(q * inv - mu_z * mu_z, 0.f);
    float mu = mu_z + b1t[k];                 // bias shifts mean, not variance
    float c1 = gamma[k] * rsqrtf(var + 1e-5f);
    g_c1[k] = c1;
    g_c2[k] = beta[k] - mu * c1;
}

// ---------------- kernel 6: fused translate_mlp GEMM2 ----------------------
// new_adjs[e, f] = elu(BN(h1[e,:])) @ W2t + b2t, h1 generated on the fly
__global__ void k_gemm2(const float* __restrict__ adjs, const float* __restrict__ flags,
                        const float* __restrict__ W1t, const float* __restrict__ W2t,
                        const float* __restrict__ b2t) {
    __shared__ float As[8][128];
    __shared__ float Bs[8][128];
    __shared__ float a0s[128], a1s[128];
    int t = threadIdx.x;
    int m0 = blockIdx.y * 128;   // edge tile
    int n0 = blockIdx.x * 128;   // output feature tile (768/128 = 6)
    int b = m0 >> 12;
    if (t < 128) {
        int e = m0 + t;
        int i = (e >> 6) & 63, j = e & 63;
        float mk = flags[b * 64 + i] * flags[b * 64 + j];
        float a = adjs[(size_t)b * 4096 + i * 64 + j];
        a0s[t] = a * mk;
        a1s[t] = (1.f - a) * mk;
    }
    __syncthreads();
    int m = t >> 1, h4 = (t & 1) * 4;
    int e = m0 + m;
    int im = (e >> 6) & 63, jm = e & 63;
    const float* pU = g_U + (size_t)(b * 64 + im) * HT + h4;
    const float* pV = g_V + (size_t)(b * 64 + jm) * HT + h4;
    float a0 = a0s[m], a1 = a1s[m];
    int kkB = t >> 5, c4 = (t & 31) * 4;
    int m_base = (t >> 4) * 8, n_base = (t & 15) * 8;

    float acc[8][8];
    #pragma unroll
    for (int a = 0; a < 8; a++)
        #pragma unroll
        for (int bq = 0; bq < 8; bq++) acc[a][bq] = 0.f;

    for (int k0 = 0; k0 < HT; k0 += 8) {
        float4 u = *(const float4*)(pU + k0);
        float4 v = *(const float4*)(pV + k0);
        float4 w0 = *(const float4*)(W1t + k0 + h4);
        float4 w1 = *(const float4*)(W1t + HT + k0 + h4);
        float4 c1 = *(const float4*)(g_c1 + k0 + h4);
        float4 c2 = *(const float4*)(g_c2 + k0 + h4);
        float4 bv = *(const float4*)(W2t + (size_t)(k0 + kkB) * 768 + n0 + c4);
        __syncthreads();
        As[h4 + 0][m] = elu_f((u.x + v.x + a0 * w0.x + a1 * w1.x) * c1.x + c2.x);
        As[h4 + 1][m] = elu_f((u.y + v.y + a0 * w0.y + a1 * w1.y) * c1.y + c2.y);
        As[h4 + 2][m] = elu_f((u.z + v.z + a0 * w0.z + a1 * w1.z) * c1.z + c2.z);
        As[h4 + 3][m] = elu_f((u.w + v.w + a0 * w0.w + a1 * w1.w) * c1.w + c2.w);
        *(float4*)&Bs[kkB][c4] = bv;
        __syncthreads();
        #pragma unroll
        for (int kk = 0; kk < 8; kk++) {
            float a[8], bb[8];
            *(float4*)(a)     = *(const float4*)&As[kk][m_base];
            *(float4*)(a + 4) = *(const float4*)&As[kk][m_base + 4];
            *(float4*)(bb)     = *(const float4*)&Bs[kk][n_base];
            *(float4*)(bb + 4) = *(const float4*)&Bs[kk][n_base + 4];
            #pragma unroll
            for (int mi = 0; mi < 8; mi++)
                #pragma unroll
                for (int ni = 0; ni < 8; ni++)
                    acc[mi][ni] += a[mi] * bb[ni];
        }
    }
    float4 bt0 = *(const float4*)(b2t + n0 + n_base);
    float4 bt1 = *(const float4*)(b2t + n0 + n_base + 4);
    #pragma unroll
    for (int mi = 0; mi < 8; mi++) {
        float* prow = g_na + (size_t)(m0 + m_base + mi) * ODIM + n0 + n_base;
        *(float4*)(prow) = make_float4(acc[mi][0] + bt0.x, acc[mi][1] + bt0.y,
                                       acc[mi][2] + bt0.z, acc[mi][3] + bt0.w);
        *(float4*)(prow + 4) = make_float4(acc[mi][4] + bt1.x, acc[mi][5] + bt1.y,
                                           acc[mi][6] + bt1.z, acc[mi][7] + bt1.w);
    }
}

// ---------------- kernel 7: fused final_read_score (GEMM3 + GEMM4) ---------
__global__ void k_score(const float* __restrict__ adjs, const float* __restrict__ flags,
                        const float* __restrict__ W1r, const float* __restrict__ b1r,
                        const float* __restrict__ W2r, const float* __restrict__ b2r,
                        float* __restrict__ out_score) {
    __shared__ float As[8][128];
    __shared__ float Bs[8][128];
    __shared__ float a0s[128], a1s[128], msks[128];
    int t = threadIdx.x;
    int m0 = blockIdx.x * 128;
    int b = m0 >> 12;
    if (t < 128) {
        int e = m0 + t;
        int i = (e >> 6) & 63, j = e & 63;
        float mk = flags[b * 64 + i] * flags[b * 64 + j];
        float a = adjs[(size_t)b * 4096 + i * 64 + j];
        a0s[t] = a * mk;
        a1s[t] = (1.f - a) * mk;
        msks[t] = mk;
    }
    __syncthreads();
    int m = t >> 1, h4 = (t & 1) * 4;
    int e_ij = m0 + m;
    int im = (e_ij >> 6) & 63, jm = e_ij & 63;
    int e_ji = b * 4096 + jm * 64 + im;
    const float* pIJ = g_na + (size_t)e_ij * ODIM + h4;
    const float* pJI = g_na + (size_t)e_ji * ODIM + h4;
    float mskm = msks[m];
    int kkB = t >> 5, c4 = (t & 31) * 4;
    int m_base = (t >> 4) * 8, n_base = (t & 15) * 8;
    float a0r[8], a1r[8];
    #pragma unroll
    for (int mi = 0; mi < 8; mi++) {
        a0r[mi] = a0s[m_base + mi];
        a1r[mi] = a1s[m_base + mi];
    }
    float score8[8];
    #pragma unroll
    for (int mi = 0; mi < 8; mi++) score8[mi] = 0.f;

    for (int nc = 0; nc < 13; nc++) {
        int n0 = nc * 128;
        float brv[8], w0v[8], w1v[8], w2v[8];
        #pragma unroll
        for (int ni = 0; ni < 8; ni++) {
            int n = n0 + n_base + ni;
            bool ok = (n < HR);
            brv[ni] = ok ? b1r[n] : 0.f;
            w0v[ni] = ok ? W1r[n] : 0.f;          // a0 channel row
            w1v[ni] = ok ? W1r[HR + n] : 0.f;     // a1 channel row
            w2v[ni] = ok ? W2r[n] : 0.f;
        }
        float acc[8][8];
        #pragma unroll
        for (int mi = 0; mi < 8; mi++)
            #pragma unroll
            for (int ni = 0; ni < 8; ni++)
                acc[mi][ni] = brv[ni] + a0r[mi] * w0v[ni] + a1r[mi] * w1v[ni];

        for (int k0 = 0; k0 < ODIM; k0 += 8) {
            float4 u = *(const float4*)(pIJ + k0);
            float4 v = *(const float4*)(pJI + k0);
            float4 bvec;
            const float* p = W1r + (size_t)(2 + k0 + kkB) * HR + n0 + c4;
            if (n0 + c4 + 3 < HR) {
                bvec = *(const float4*)p;
            } else {
                bvec.x = (n0 + c4 + 0 < HR) ? p[0] : 0.f;
                bvec.y = (n0 + c4 + 1 < HR) ? p[1] : 0.f;
                bvec.z = (n0 + c4 + 2 < HR) ? p[2] : 0.f;
                bvec.w = (n0 + c4 + 3 < HR) ? p[3] : 0.f;
            }
            __syncthreads();
            As[h4 + 0][m] = (u.x + v.x) * mskm;
            As[h4 + 1][m] = (u.y + v.y) * mskm;
            As[h4 + 2][m] = (u.z + v.z) * mskm;
            As[h4 + 3][m] = (u.w + v.w) * mskm;
            *(float4*)&Bs[kkB][c4] = bvec;
            __syncthreads();
            #pragma unroll
            for (int kk = 0; kk < 8; kk++) {
                float a[8], bb[8];
                *(float4*)(a)     = *(const float4*)&As[kk][m_base];
                *(float4*)(a + 4) = *(const float4*)&As[kk][m_base + 4];
                *(float4*)(bb)     = *(const float4*)&Bs[kk][n_base];
                *(float4*)(bb + 4) = *(const float4*)&Bs[kk][n_base + 4];
                #pragma unroll
                for (int mi = 0; mi < 8; mi++)
                    #pragma unroll
                    for (int ni = 0; ni < 8; ni++)
                        acc[mi][ni] += a[mi] * bb[ni];
            }
        }
        #pragma unroll
        for (int mi = 0; mi < 8; mi++)
            #pragma unroll
            for (int ni = 0; ni < 8; ni++)
                score8[mi] += elu_f(acc[mi][ni]) * w2v[ni];
    }
    // reduce over the 16 threads (tx) that share each row group
    #pragma unroll
    for (int off = 8; off > 0; off >>= 1)
        #pragma unroll
        for (int mi = 0; mi < 8; mi++)
            score8[mi] += __shfl_xor_sync(0xffffffffu, score8[mi], off);
    if ((t & 15) == 0) {
        float b2 = b2r[0];
        #pragma unroll
        for (int mi = 0; mi < 8; mi++) {
            int e = m0 + m_base + mi;
            int i = (e >> 6) & 63, j = e & 63;
            out_score[e] = (i == j) ? 0.f : (score8[mi] + b2);
        }
    }
}

// ---------------- launch -----------------------------------------------------
extern "C" void kernel_launch(void* const* d_in, const int* in_sizes, int n_in,
                              void* d_out, int out_size) {
    const float* x     = (const float*)d_in[0];
    const float* adjs  = (const float*)d_in[1];
    const float* flags = (const float*)d_in[2];
    const float* Wg    = (const float*)d_in[3];
    const float* bg    = (const float*)d_in[4];
    const float* Wout  = (const float*)d_in[5];
    const float* bout  = (const float*)d_in[6];
    const float* W1t   = (const float*)d_in[7];
    const float* b1t   = (const float*)d_in[8];
    const float* gamma = (const float*)d_in[9];
    const float* beta  = (const float*)d_in[10];
    const float* W2t   = (const float*)d_in[11];
    const float* b2t   = (const float*)d_in[12];
    const float* W1r   = (const float*)d_in[13];
    const float* b1r   = (const float*)d_in[14];
    const float* W2r   = (const float*)d_in[15];
    const float* b2r   = (const float*)d_in[16];

    float* out_score = (float*)d_out;             // [B,N,N] = 65536
    float* out_xo    = (float*)d_out + NEDGE;     // [B,N,768]

    k_agg<<<NROW, 128>>>(x, adjs, flags);
    k_gin<<<NROW / 8, 256>>>(x, flags, Wg, bg, Wout, bout, out_xo);
    k_uv<<<dim3(24, 8), 256>>>(out_xo, W1t);
    k_stats<<<NROW, 256>>>(adjs, flags, W1t);
    k_stats2<<<6, 256>>>(b1t, gamma, beta);
    k_gemm2<<<dim3(6, 512), 256>>>(adjs, flags, W1t, W2t, b2t);
    k_score<<<512, 256>>>(adjs, flags, W1r, b1r, W2r, b2r, out_score);
}